// round 1
// baseline (speedup 1.0000x reference)
#include <cuda_runtime.h>

// Problem constants
#define Bv 2
#define Sv 2048
#define Dv 1024
#define Hv 32
#define HDv 32
#define Mv (Bv*Sv)   // 4096

// Scratch (device globals -- no allocation allowed)
__device__ float g_Q[Bv*Hv*Sv*HDv];   // [b,h,s,hd]
__device__ float g_K[Bv*Hv*Sv*HDv];
__device__ float g_V[Bv*Hv*Sv*HDv];
__device__ float g_O[Mv*Dv];          // [b*s, h*hd] row-major

// ---------------------------------------------------------------------------
// NT GEMM: C[m,n] = sum_k A[m,k] * W[n,k];  M=4096, N=1024, K=1024.
// mode 0: C standard [M][N] row-major
// mode 1: C head-split: b=m/S, s=m%S, h=n/HD, hd=n%HD -> [((b*H+h)*S+s)*HD+hd]
// Block 64x64 tile, BK=16, 256 threads (16x16), 4x4 micro-tile per thread.
// ---------------------------------------------------------------------------
__global__ __launch_bounds__(256) void gemm64_nt(
    const float* __restrict__ A, const float* __restrict__ W,
    float* __restrict__ C, int mode)
{
    __shared__ float As[16][64];
    __shared__ float Bs[16][64];

    const int K = Dv;
    const int tx = threadIdx.x, ty = threadIdx.y;
    const int tid = ty * 16 + tx;
    const int m0 = blockIdx.y * 64;
    const int n0 = blockIdx.x * 64;

    const int lrow = tid >> 2;          // 0..63
    const int lcg  = (tid & 3) * 4;     // 0,4,8,12

    const float* Aptr = A + (size_t)(m0 + lrow) * K + lcg;
    const float* Wptr = W + (size_t)(n0 + lrow) * K + lcg;

    float acc[4][4];
    #pragma unroll
    for (int i = 0; i < 4; i++)
        #pragma unroll
        for (int j = 0; j < 4; j++) acc[i][j] = 0.f;

    for (int k0 = 0; k0 < K; k0 += 16) {
        float4 av = *(const float4*)(Aptr + k0);
        float4 wv = *(const float4*)(Wptr + k0);
        __syncthreads();
        As[lcg + 0][lrow] = av.x; As[lcg + 1][lrow] = av.y;
        As[lcg + 2][lrow] = av.z; As[lcg + 3][lrow] = av.w;
        Bs[lcg + 0][lrow] = wv.x; Bs[lcg + 1][lrow] = wv.y;
        Bs[lcg + 2][lrow] = wv.z; Bs[lcg + 3][lrow] = wv.w;
        __syncthreads();

        #pragma unroll
        for (int kk = 0; kk < 16; kk++) {
            float4 a4 = *(const float4*)&As[kk][ty * 4];
            float4 b4 = *(const float4*)&Bs[kk][tx * 4];
            float ar[4] = {a4.x, a4.y, a4.z, a4.w};
            float br[4] = {b4.x, b4.y, b4.z, b4.w};
            #pragma unroll
            for (int i = 0; i < 4; i++)
                #pragma unroll
                for (int j = 0; j < 4; j++)
                    acc[i][j] += ar[i] * br[j];
        }
    }

    #pragma unroll
    for (int i = 0; i < 4; i++) {
        int m = m0 + ty * 4 + i;
        #pragma unroll
        for (int j = 0; j < 4; j++) {
            int n = n0 + tx * 4 + j;
            if (mode == 0) {
                C[(size_t)m * Dv + n] = acc[i][j];
            } else {
                int b = m / Sv, s = m % Sv;
                int h = n / HDv, hd = n % HDv;
                C[(size_t)((b * Hv + h) * Sv + s) * HDv + hd] = acc[i][j];
            }
        }
    }
}

// ---------------------------------------------------------------------------
// Causal flash attention with per-(h,q) SSMax scale.
// Block: 128 threads, one query row per thread (BQ=128). KV tiles of 64 rows
// staged in smem; inner processing in 32-key chunks to bound register use.
// grid = (S/128, H, B)
// ---------------------------------------------------------------------------
__global__ __launch_bounds__(128) void flash_attn(
    const float* __restrict__ Qg, const float* __restrict__ Kg,
    const float* __restrict__ Vg, float* __restrict__ Og,
    const float* __restrict__ slog, const float* __restrict__ sscale)
{
    __shared__ float Ks[64 * 32];
    __shared__ float Vs[64 * 32];

    const int tid = threadIdx.x;           // 0..127
    const int q0  = blockIdx.x * 128;
    const int h   = blockIdx.y;
    const int b   = blockIdx.z;
    const int q   = q0 + tid;

    const float* qp = Qg + (size_t)((b * Hv + h) * Sv + q) * HDv;
    float qr[32];
    #pragma unroll
    for (int i = 0; i < 8; i++) {
        float4 t = ((const float4*)qp)[i];
        qr[4*i+0] = t.x; qr[4*i+1] = t.y; qr[4*i+2] = t.z; qr[4*i+3] = t.w;
    }

    const float scale = slog[q] * sscale[h] * 0.17677669529663687f; // 1/sqrt(32)

    float m = -1e30f, l = 0.f;
    float acc[32];
    #pragma unroll
    for (int d = 0; d < 32; d++) acc[d] = 0.f;

    const float* kbase = Kg + (size_t)(b * Hv + h) * Sv * HDv;
    const float* vbase = Vg + (size_t)(b * Hv + h) * Sv * HDv;

    const int ktiles = q0 / 64 + 2;   // covers keys [0, q0+127]

    for (int kt = 0; kt < ktiles; kt++) {
        const int kv0 = kt * 64;
        __syncthreads();
        {
            const float4* kf = (const float4*)(kbase + (size_t)kv0 * HDv);
            const float4* vf = (const float4*)(vbase + (size_t)kv0 * HDv);
            float4* ksf = (float4*)Ks;
            float4* vsf = (float4*)Vs;
            #pragma unroll
            for (int i = 0; i < 4; i++) {
                ksf[tid + i * 128] = kf[tid + i * 128];
                vsf[tid + i * 128] = vf[tid + i * 128];
            }
        }
        __syncthreads();

        #pragma unroll
        for (int c = 0; c < 64; c += 32) {
            float sv[32];
            #pragma unroll
            for (int j = 0; j < 32; j++) {
                const float4* kr = (const float4*)(Ks + (c + j) * 32);
                float s = 0.f;
                #pragma unroll
                for (int d4 = 0; d4 < 8; d4++) {
                    float4 kv = kr[d4];
                    s += qr[4*d4+0] * kv.x + qr[4*d4+1] * kv.y
                       + qr[4*d4+2] * kv.z + qr[4*d4+3] * kv.w;
                }
                int kidx = kv0 + c + j;
                sv[j] = (kidx <= q) ? s * scale : -1e30f;
            }

            float mloc = m;
            #pragma unroll
            for (int j = 0; j < 32; j++) mloc = fmaxf(mloc, sv[j]);
            float corr = __expf(m - mloc);
            m = mloc;
            l *= corr;
            #pragma unroll
            for (int d = 0; d < 32; d++) acc[d] *= corr;

            #pragma unroll
            for (int j = 0; j < 32; j++) {
                float p = __expf(sv[j] - m);
                l += p;
                const float4* vr = (const float4*)(Vs + (c + j) * 32);
                #pragma unroll
                for (int d4 = 0; d4 < 8; d4++) {
                    float4 vv = vr[d4];
                    acc[4*d4+0] += p * vv.x; acc[4*d4+1] += p * vv.y;
                    acc[4*d4+2] += p * vv.z; acc[4*d4+3] += p * vv.w;
                }
            }
        }
    }

    const float inv = 1.f / l;
    float* op = Og + (size_t)(b * Sv + q) * Dv + h * HDv;
    #pragma unroll
    for (int i = 0; i < 8; i++) {
        float4 t;
        t.x = acc[4*i+0] * inv; t.y = acc[4*i+1] * inv;
        t.z = acc[4*i+2] * inv; t.w = acc[4*i+3] * inv;
        ((float4*)op)[i] = t;
    }
}

// ---------------------------------------------------------------------------
extern "C" void kernel_launch(void* const* d_in, const int* in_sizes, int n_in,
                              void* d_out, int out_size)
{
    const float* x      = (const float*)d_in[0];
    // d_in[1] = mask (additive causal, -1e9 above diag) -- handled analytically
    const float* slog   = (const float*)d_in[2];
    const float* wq     = (const float*)d_in[3];
    const float* wk     = (const float*)d_in[4];
    const float* wv     = (const float*)d_in[5];
    const float* wo     = (const float*)d_in[6];
    const float* sscale = (const float*)d_in[7];
    float* out = (float*)d_out;

    float *Qp, *Kp, *Vp, *Op;
    cudaGetSymbolAddress((void**)&Qp, g_Q);
    cudaGetSymbolAddress((void**)&Kp, g_K);
    cudaGetSymbolAddress((void**)&Vp, g_V);
    cudaGetSymbolAddress((void**)&Op, g_O);

    dim3 gblk(16, 16);
    dim3 ggrd(Dv / 64, Mv / 64);   // (16, 64)

    gemm64_nt<<<ggrd, gblk>>>(x, wq, Qp, 1);
    gemm64_nt<<<ggrd, gblk>>>(x, wk, Kp, 1);
    gemm64_nt<<<ggrd, gblk>>>(x, wv, Vp, 1);

    dim3 fgrd(Sv / 128, Hv, Bv);   // (16, 32, 2)
    flash_attn<<<fgrd, 128>>>(Qp, Kp, Vp, Op, slog, sscale);

    gemm64_nt<<<ggrd, gblk>>>(Op, wo, out, 0);
}

// round 4
// speedup vs baseline: 1.2740x; 1.2740x over previous
#include <cuda_runtime.h>
#include <cstdint>

// Problem constants
#define Bv 2
#define Sv 2048
#define Dv 1024
#define Hv 32
#define HDv 32
#define Mv (Bv*Sv)   // 4096

// Scratch (device globals -- no allocation allowed)
__device__ float g_Q[Bv*Hv*Sv*HDv];   // [b,h,s,hd]
__device__ float g_K[Bv*Hv*Sv*HDv];
__device__ float g_V[Bv*Hv*Sv*HDv];
__device__ float g_O[Mv*Dv];          // [b*s, h*hd] row-major

// ---------------------------------------------------------------------------
// tf32 helpers (legacy mma.sync path -- works on plain sm_103 target)
// ---------------------------------------------------------------------------
__device__ __forceinline__ uint32_t f32_to_tf32(float f) {
    uint32_t u;
    asm("cvt.rna.tf32.f32 %0, %1;" : "=r"(u) : "f"(f));
    return u;
}

// D(16x8,f32) += A(16x8,tf32,row) * B(8x8,tf32,col)
__device__ __forceinline__ void mma16n8k8(float* d, const uint32_t* a, const uint32_t* b) {
    asm volatile(
        "mma.sync.aligned.m16n8k8.row.col.f32.tf32.tf32.f32 "
        "{%0,%1,%2,%3}, {%4,%5,%6,%7}, {%8,%9}, {%0,%1,%2,%3};"
        : "+f"(d[0]), "+f"(d[1]), "+f"(d[2]), "+f"(d[3])
        : "r"(a[0]), "r"(a[1]), "r"(a[2]), "r"(a[3]), "r"(b[0]), "r"(b[1]));
}

// split a into tf32 hi + tf32 lo (3xTF32 compensation)
__device__ __forceinline__ void split_tf32(float a, uint32_t& hi, uint32_t& lo) {
    hi = f32_to_tf32(a);
    lo = f32_to_tf32(a - __uint_as_float(hi));
}

// ---------------------------------------------------------------------------
// Tensor-core NT GEMM (3xTF32): C[m,n] = sum_k A[m,k] * W[n,k]
// M=4096, N=1024, K=1024. CTA tile 128x128, K-chunk 32, 8 warps (4m x 2n),
// warp tile 32x64. Smem holds raw fp32 (stride 36: conflict-free).
// Per fragment pair: acc += hi*hi + hi*lo + lo*hi  (lo*lo ~ 2e-7, dropped).
// mode 0: C row-major [M][Dv]; mode 1: head-split [b,h,s,hd].
// ---------------------------------------------------------------------------
__global__ __launch_bounds__(256) void gemm_mma(
    const float* __restrict__ A, const float* __restrict__ W,
    float* __restrict__ C, int mode)
{
    __shared__ float As[128][36];
    __shared__ float Bs[128][36];

    const int tid  = threadIdx.x;
    const int wid  = tid >> 5, lane = tid & 31;
    const int wm   = wid & 3,  wn   = wid >> 2;     // warp grid 4 x 2
    const int g    = lane >> 2, tg  = lane & 3;     // groupID / thread-in-group
    const int m0   = blockIdx.y * 128;
    const int n0   = blockIdx.x * 128;

    // gmem staging map: idx = tid + j*256 -> row = idx>>3 (0..127 via +32j), c4 = idx&7
    const int lrow = tid >> 3;    // 0..31
    const int lc4  = tid & 7;     // float4 slot within 32-float chunk
    const float* Ap = A + (size_t)(m0 + lrow) * Dv + lc4 * 4;
    const float* Wp = W + (size_t)(n0 + lrow) * Dv + lc4 * 4;

    float acc[2][8][4];
    #pragma unroll
    for (int mt = 0; mt < 2; mt++)
        #pragma unroll
        for (int nt = 0; nt < 8; nt++)
            #pragma unroll
            for (int i = 0; i < 4; i++) acc[mt][nt][i] = 0.f;

    float4 ra[4], rb[4];

    // prefetch chunk 0 (raw fp32)
    #pragma unroll
    for (int j = 0; j < 4; j++) {
        ra[j] = *(const float4*)(Ap + (size_t)(32 * j) * Dv);
        rb[j] = *(const float4*)(Wp + (size_t)(32 * j) * Dv);
    }

    for (int c = 0; c < 32; c++) {
        __syncthreads();   // previous chunk's compute done reading smem
        #pragma unroll
        for (int j = 0; j < 4; j++) {
            *(float4*)&As[lrow + 32 * j][lc4 * 4] = ra[j];
            *(float4*)&Bs[lrow + 32 * j][lc4 * 4] = rb[j];
        }
        __syncthreads();

        if (c < 31) {
            const int k0 = (c + 1) * 32;
            #pragma unroll
            for (int j = 0; j < 4; j++) {
                ra[j] = *(const float4*)(Ap + (size_t)(32 * j) * Dv + k0);
                rb[j] = *(const float4*)(Wp + (size_t)(32 * j) * Dv + k0);
            }
        }

        #pragma unroll
        for (int ks = 0; ks < 4; ks++) {
            const int kb = ks * 8;
            uint32_t ah[2][4], al[2][4], bh[8][2], bl[8][2];
            #pragma unroll
            for (int mt = 0; mt < 2; mt++) {
                const int r = wm * 32 + mt * 16;
                split_tf32(As[r + g    ][kb + tg    ], ah[mt][0], al[mt][0]);
                split_tf32(As[r + g + 8][kb + tg    ], ah[mt][1], al[mt][1]);
                split_tf32(As[r + g    ][kb + tg + 4], ah[mt][2], al[mt][2]);
                split_tf32(As[r + g + 8][kb + tg + 4], ah[mt][3], al[mt][3]);
            }
            #pragma unroll
            for (int nt = 0; nt < 8; nt++) {
                const int n = wn * 64 + nt * 8 + g;
                split_tf32(Bs[n][kb + tg    ], bh[nt][0], bl[nt][0]);
                split_tf32(Bs[n][kb + tg + 4], bh[nt][1], bl[nt][1]);
            }
            #pragma unroll
            for (int mt = 0; mt < 2; mt++)
                #pragma unroll
                for (int nt = 0; nt < 8; nt++) {
                    mma16n8k8(acc[mt][nt], ah[mt], bl[nt]);  // hi*lo
                    mma16n8k8(acc[mt][nt], al[mt], bh[nt]);  // lo*hi
                    mma16n8k8(acc[mt][nt], ah[mt], bh[nt]);  // hi*hi
                }
        }
    }

    // Epilogue: c0 (row g, col 2tg), c1 (+1 col), c2/c3 (row g+8)
    #pragma unroll
    for (int mt = 0; mt < 2; mt++) {
        #pragma unroll
        for (int nt = 0; nt < 8; nt++) {
            const int m = m0 + wm * 32 + mt * 16 + g;
            const int n = n0 + wn * 64 + nt * 8 + tg * 2;
            if (mode == 0) {
                float2* p0 = (float2*)(C + (size_t)m * Dv + n);
                float2* p1 = (float2*)(C + (size_t)(m + 8) * Dv + n);
                *p0 = make_float2(acc[mt][nt][0], acc[mt][nt][1]);
                *p1 = make_float2(acc[mt][nt][2], acc[mt][nt][3]);
            } else {
                const int h = n / HDv, hd = n % HDv;   // n, n+1 same head (hd even)
                const int b0_ = m / Sv, s0_ = m % Sv;
                const int b1_ = (m + 8) / Sv, s1_ = (m + 8) % Sv;
                float2* p0 = (float2*)(C + (size_t)((b0_ * Hv + h) * Sv + s0_) * HDv + hd);
                float2* p1 = (float2*)(C + (size_t)((b1_ * Hv + h) * Sv + s1_) * HDv + hd);
                *p0 = make_float2(acc[mt][nt][0], acc[mt][nt][1]);
                *p1 = make_float2(acc[mt][nt][2], acc[mt][nt][3]);
            }
        }
    }
}

// ---------------------------------------------------------------------------
// Causal flash attention with per-(h,q) SSMax scale (unchanged; passing).
// ---------------------------------------------------------------------------
__global__ __launch_bounds__(128) void flash_attn(
    const float* __restrict__ Qg, const float* __restrict__ Kg,
    const float* __restrict__ Vg, float* __restrict__ Og,
    const float* __restrict__ slog, const float* __restrict__ sscale)
{
    __shared__ float Ks[64 * 32];
    __shared__ float Vs[64 * 32];

    const int tid = threadIdx.x;
    const int q0  = blockIdx.x * 128;
    const int h   = blockIdx.y;
    const int b   = blockIdx.z;
    const int q   = q0 + tid;

    const float* qp = Qg + (size_t)((b * Hv + h) * Sv + q) * HDv;
    float qr[32];
    #pragma unroll
    for (int i = 0; i < 8; i++) {
        float4 t = ((const float4*)qp)[i];
        qr[4*i+0] = t.x; qr[4*i+1] = t.y; qr[4*i+2] = t.z; qr[4*i+3] = t.w;
    }

    const float scale = slog[q] * sscale[h] * 0.17677669529663687f; // 1/sqrt(32)

    float m = -1e30f, l = 0.f;
    float acc[32];
    #pragma unroll
    for (int d = 0; d < 32; d++) acc[d] = 0.f;

    const float* kbase = Kg + (size_t)(b * Hv + h) * Sv * HDv;
    const float* vbase = Vg + (size_t)(b * Hv + h) * Sv * HDv;

    const int ktiles = q0 / 64 + 2;

    for (int kt = 0; kt < ktiles; kt++) {
        const int kv0 = kt * 64;
        __syncthreads();
        {
            const float4* kf = (const float4*)(kbase + (size_t)kv0 * HDv);
            const float4* vf = (const float4*)(vbase + (size_t)kv0 * HDv);
            float4* ksf = (float4*)Ks;
            float4* vsf = (float4*)Vs;
            #pragma unroll
            for (int i = 0; i < 4; i++) {
                ksf[tid + i * 128] = kf[tid + i * 128];
                vsf[tid + i * 128] = vf[tid + i * 128];
            }
        }
        __syncthreads();

        #pragma unroll
        for (int c = 0; c < 64; c += 32) {
            float sv[32];
            #pragma unroll
            for (int j = 0; j < 32; j++) {
                const float4* kr = (const float4*)(Ks + (c + j) * 32);
                float s = 0.f;
                #pragma unroll
                for (int d4 = 0; d4 < 8; d4++) {
                    float4 kv = kr[d4];
                    s += qr[4*d4+0] * kv.x + qr[4*d4+1] * kv.y
                       + qr[4*d4+2] * kv.z + qr[4*d4+3] * kv.w;
                }
                int kidx = kv0 + c + j;
                sv[j] = (kidx <= q) ? s * scale : -1e30f;
            }

            float mloc = m;
            #pragma unroll
            for (int j = 0; j < 32; j++) mloc = fmaxf(mloc, sv[j]);
            float corr = __expf(m - mloc);
            m = mloc;
            l *= corr;
            #pragma unroll
            for (int d = 0; d < 32; d++) acc[d] *= corr;

            #pragma unroll
            for (int j = 0; j < 32; j++) {
                float p = __expf(sv[j] - m);
                l += p;
                const float4* vr = (const float4*)(Vs + (c + j) * 32);
                #pragma unroll
                for (int d4 = 0; d4 < 8; d4++) {
                    float4 vv = vr[d4];
                    acc[4*d4+0] += p * vv.x; acc[4*d4+1] += p * vv.y;
                    acc[4*d4+2] += p * vv.z; acc[4*d4+3] += p * vv.w;
                }
            }
        }
    }

    const float inv = 1.f / l;
    float* op = Og + (size_t)(b * Sv + q) * Dv + h * HDv;
    #pragma unroll
    for (int i = 0; i < 8; i++) {
        float4 t;
        t.x = acc[4*i+0] * inv; t.y = acc[4*i+1] * inv;
        t.z = acc[4*i+2] * inv; t.w = acc[4*i+3] * inv;
        ((float4*)op)[i] = t;
    }
}

// ---------------------------------------------------------------------------
extern "C" void kernel_launch(void* const* d_in, const int* in_sizes, int n_in,
                              void* d_out, int out_size)
{
    const float* x      = (const float*)d_in[0];
    // d_in[1] = mask (additive causal, -1e9 above diag) -- handled analytically
    const float* slog   = (const float*)d_in[2];
    const float* wq     = (const float*)d_in[3];
    const float* wk     = (const float*)d_in[4];
    const float* wv     = (const float*)d_in[5];
    const float* wo     = (const float*)d_in[6];
    const float* sscale = (const float*)d_in[7];
    float* out = (float*)d_out;

    float *Qp, *Kp, *Vp, *Op;
    cudaGetSymbolAddress((void**)&Qp, g_Q);
    cudaGetSymbolAddress((void**)&Kp, g_K);
    cudaGetSymbolAddress((void**)&Vp, g_V);
    cudaGetSymbolAddress((void**)&Op, g_O);

    dim3 ggrd(Dv / 128, Mv / 128);   // (8, 32) = 256 CTAs

    gemm_mma<<<ggrd, 256>>>(x, wq, Qp, 1);
    gemm_mma<<<ggrd, 256>>>(x, wk, Kp, 1);
    gemm_mma<<<ggrd, 256>>>(x, wv, Vp, 1);

    dim3 fgrd(Sv / 128, Hv, Bv);     // (16, 32, 2)
    flash_attn<<<fgrd, 128>>>(Qp, Kp, Vp, Op, slog, sscale);

    gemm_mma<<<ggrd, 256>>>(Op, wo, out, 0);
}

// round 5
// speedup vs baseline: 2.0529x; 1.6114x over previous
#include <cuda_runtime.h>
#include <cstdint>

// Problem constants
#define Bv 2
#define Sv 2048
#define Dv 1024
#define Hv 32
#define HDv 32
#define Mv (Bv*Sv)   // 4096

// Scratch (device globals -- no allocation allowed)
__device__ float g_Q[Bv*Hv*Sv*HDv];   // [b,h,s,hd]
__device__ float g_K[Bv*Hv*Sv*HDv];
__device__ float g_V[Bv*Hv*Sv*HDv];
__device__ float g_O[Mv*Dv];          // [b*s, h*hd] row-major

// ---------------------------------------------------------------------------
// tf32 helpers (legacy mma.sync path -- works on plain sm_103 target)
// ---------------------------------------------------------------------------
__device__ __forceinline__ uint32_t f32_to_tf32(float f) {
    uint32_t u;
    asm("cvt.rna.tf32.f32 %0, %1;" : "=r"(u) : "f"(f));
    return u;
}

// D(16x8,f32) += A(16x8,tf32,row) * B(8x8,tf32,col)
__device__ __forceinline__ void mma16n8k8(float* d, const uint32_t* a, const uint32_t* b) {
    asm volatile(
        "mma.sync.aligned.m16n8k8.row.col.f32.tf32.tf32.f32 "
        "{%0,%1,%2,%3}, {%4,%5,%6,%7}, {%8,%9}, {%0,%1,%2,%3};"
        : "+f"(d[0]), "+f"(d[1]), "+f"(d[2]), "+f"(d[3])
        : "r"(a[0]), "r"(a[1]), "r"(a[2]), "r"(a[3]), "r"(b[0]), "r"(b[1]));
}

// split a into tf32 hi + tf32 lo (3xTF32 compensation)
__device__ __forceinline__ void split_tf32(float a, uint32_t& hi, uint32_t& lo) {
    hi = f32_to_tf32(a);
    lo = f32_to_tf32(a - __uint_as_float(hi));
}

// ---------------------------------------------------------------------------
// Tensor-core NT GEMM (3xTF32): C[m,n] = sum_k A[m,k] * W[n,k]
// (unchanged from R3 -- verified passing)
// ---------------------------------------------------------------------------
__global__ __launch_bounds__(256) void gemm_mma(
    const float* __restrict__ A, const float* __restrict__ W,
    float* __restrict__ C, int mode)
{
    __shared__ float As[128][36];
    __shared__ float Bs[128][36];

    const int tid  = threadIdx.x;
    const int wid  = tid >> 5, lane = tid & 31;
    const int wm   = wid & 3,  wn   = wid >> 2;     // warp grid 4 x 2
    const int g    = lane >> 2, tg  = lane & 3;     // groupID / thread-in-group
    const int m0   = blockIdx.y * 128;
    const int n0   = blockIdx.x * 128;

    const int lrow = tid >> 3;    // 0..31
    const int lc4  = tid & 7;     // float4 slot within 32-float chunk
    const float* Ap = A + (size_t)(m0 + lrow) * Dv + lc4 * 4;
    const float* Wp = W + (size_t)(n0 + lrow) * Dv + lc4 * 4;

    float acc[2][8][4];
    #pragma unroll
    for (int mt = 0; mt < 2; mt++)
        #pragma unroll
        for (int nt = 0; nt < 8; nt++)
            #pragma unroll
            for (int i = 0; i < 4; i++) acc[mt][nt][i] = 0.f;

    float4 ra[4], rb[4];
    #pragma unroll
    for (int j = 0; j < 4; j++) {
        ra[j] = *(const float4*)(Ap + (size_t)(32 * j) * Dv);
        rb[j] = *(const float4*)(Wp + (size_t)(32 * j) * Dv);
    }

    for (int c = 0; c < 32; c++) {
        __syncthreads();
        #pragma unroll
        for (int j = 0; j < 4; j++) {
            *(float4*)&As[lrow + 32 * j][lc4 * 4] = ra[j];
            *(float4*)&Bs[lrow + 32 * j][lc4 * 4] = rb[j];
        }
        __syncthreads();

        if (c < 31) {
            const int k0 = (c + 1) * 32;
            #pragma unroll
            for (int j = 0; j < 4; j++) {
                ra[j] = *(const float4*)(Ap + (size_t)(32 * j) * Dv + k0);
                rb[j] = *(const float4*)(Wp + (size_t)(32 * j) * Dv + k0);
            }
        }

        #pragma unroll
        for (int ks = 0; ks < 4; ks++) {
            const int kb = ks * 8;
            uint32_t ah[2][4], al[2][4], bh[8][2], bl[8][2];
            #pragma unroll
            for (int mt = 0; mt < 2; mt++) {
                const int r = wm * 32 + mt * 16;
                split_tf32(As[r + g    ][kb + tg    ], ah[mt][0], al[mt][0]);
                split_tf32(As[r + g + 8][kb + tg    ], ah[mt][1], al[mt][1]);
                split_tf32(As[r + g    ][kb + tg + 4], ah[mt][2], al[mt][2]);
                split_tf32(As[r + g + 8][kb + tg + 4], ah[mt][3], al[mt][3]);
            }
            #pragma unroll
            for (int nt = 0; nt < 8; nt++) {
                const int n = wn * 64 + nt * 8 + g;
                split_tf32(Bs[n][kb + tg    ], bh[nt][0], bl[nt][0]);
                split_tf32(Bs[n][kb + tg + 4], bh[nt][1], bl[nt][1]);
            }
            #pragma unroll
            for (int mt = 0; mt < 2; mt++)
                #pragma unroll
                for (int nt = 0; nt < 8; nt++) {
                    mma16n8k8(acc[mt][nt], ah[mt], bl[nt]);  // hi*lo
                    mma16n8k8(acc[mt][nt], al[mt], bh[nt]);  // lo*hi
                    mma16n8k8(acc[mt][nt], ah[mt], bh[nt]);  // hi*hi
                }
        }
    }

    #pragma unroll
    for (int mt = 0; mt < 2; mt++) {
        #pragma unroll
        for (int nt = 0; nt < 8; nt++) {
            const int m = m0 + wm * 32 + mt * 16 + g;
            const int n = n0 + wn * 64 + nt * 8 + tg * 2;
            if (mode == 0) {
                float2* p0 = (float2*)(C + (size_t)m * Dv + n);
                float2* p1 = (float2*)(C + (size_t)(m + 8) * Dv + n);
                *p0 = make_float2(acc[mt][nt][0], acc[mt][nt][1]);
                *p1 = make_float2(acc[mt][nt][2], acc[mt][nt][3]);
            } else {
                const int h = n / HDv, hd = n % HDv;
                const int b0_ = m / Sv, s0_ = m % Sv;
                const int b1_ = (m + 8) / Sv, s1_ = (m + 8) % Sv;
                float2* p0 = (float2*)(C + (size_t)((b0_ * Hv + h) * Sv + s0_) * HDv + hd);
                float2* p1 = (float2*)(C + (size_t)((b1_ * Hv + h) * Sv + s1_) * HDv + hd);
                *p0 = make_float2(acc[mt][nt][0], acc[mt][nt][1]);
                *p1 = make_float2(acc[mt][nt][2], acc[mt][nt][3]);
            }
        }
    }
}

// ---------------------------------------------------------------------------
// Tensor-core causal flash attention.
// CTA: 64 q-rows, 4 warps; warp tile 16q x 128k. KV blocks of 128 in smem.
// QK^T: 3xTF32 (scores fp32-accurate; per-row SSMax scale folded into Q).
// P*V:  1xTF32 (P in [0,1], sum=1 -> unbiased rounding, ~1e-4 norm error).
// Online softmax in registers; P accum->A-frag layout via shfl.
// grid = (S/64, H, B), 128 threads.
// ---------------------------------------------------------------------------
__global__ __launch_bounds__(128) void flash_mma(
    const float* __restrict__ Qg, const float* __restrict__ Kg,
    const float* __restrict__ Vg, float* __restrict__ Og,
    const float* __restrict__ slog, const float* __restrict__ sscale)
{
    __shared__ float Ks[128][36];   // QK B-frag banks: 4g+tg (conflict-free)
    __shared__ float Vs[128][40];   // PV B-frag banks: 8tg+g (conflict-free)

    const int tid  = threadIdx.x;
    const int wid  = tid >> 5, lane = tid & 31;
    const int g    = lane >> 2, tg  = lane & 3;
    const int q0   = blockIdx.x * 64;
    const int h    = blockIdx.y, b = blockIdx.z;

    const float* qbase = Qg + (size_t)(b * Hv + h) * Sv * HDv;
    const float* kbase = Kg + (size_t)(b * Hv + h) * Sv * HDv;
    const float* vbase = Vg + (size_t)(b * Hv + h) * Sv * HDv;

    const int r0 = q0 + wid * 16 + g;   // rows this thread owns (c0,c1)
    const int r1 = r0 + 8;              // (c2,c3)

    const float sc0 = slog[r0] * sscale[h] * 0.17677669529663687f;
    const float sc1 = slog[r1] * sscale[h] * 0.17677669529663687f;

    // Q fragments (scaled, hi/lo split). kc = 8-wide k-chunk of head dim.
    uint32_t qh[4][4], ql[4][4];
    #pragma unroll
    for (int kc = 0; kc < 4; kc++) {
        float v0 = qbase[(size_t)r0 * HDv + kc * 8 + tg    ] * sc0;
        float v1 = qbase[(size_t)r1 * HDv + kc * 8 + tg    ] * sc1;
        float v2 = qbase[(size_t)r0 * HDv + kc * 8 + tg + 4] * sc0;
        float v3 = qbase[(size_t)r1 * HDv + kc * 8 + tg + 4] * sc1;
        split_tf32(v0, qh[kc][0], ql[kc][0]);
        split_tf32(v1, qh[kc][1], ql[kc][1]);
        split_tf32(v2, qh[kc][2], ql[kc][2]);
        split_tf32(v3, qh[kc][3], ql[kc][3]);
    }

    float m0 = -1e30f, m1 = -1e30f, l0 = 0.f, l1 = 0.f;
    float o[4][4];
    #pragma unroll
    for (int nt2 = 0; nt2 < 4; nt2++)
        #pragma unroll
        for (int i = 0; i < 4; i++) o[nt2][i] = 0.f;

    const int nblocks = (q0 + 64 + 127) / 128;

    for (int kt = 0; kt < nblocks; kt++) {
        const int kv0 = kt * 128;
        __syncthreads();
        #pragma unroll
        for (int j = 0; j < 8; j++) {
            const int idx = tid + j * 128;
            const int row = idx >> 3, c4 = idx & 7;
            *(float4*)&Ks[row][c4 * 4] = *(const float4*)(kbase + (size_t)(kv0 + row) * HDv + c4 * 4);
            *(float4*)&Vs[row][c4 * 4] = *(const float4*)(vbase + (size_t)(kv0 + row) * HDv + c4 * 4);
        }
        __syncthreads();

        // S = Q K^T (3xTF32). s[nt] covers key cols [kv0+nt*8, kv0+nt*8+8)
        float s[16][4];
        #pragma unroll
        for (int nt = 0; nt < 16; nt++)
            #pragma unroll
            for (int i = 0; i < 4; i++) s[nt][i] = 0.f;

        #pragma unroll
        for (int kc = 0; kc < 4; kc++) {
            #pragma unroll
            for (int nt = 0; nt < 16; nt++) {
                uint32_t bh[2], bl[2];
                split_tf32(Ks[nt * 8 + g][kc * 8 + tg    ], bh[0], bl[0]);
                split_tf32(Ks[nt * 8 + g][kc * 8 + tg + 4], bh[1], bl[1]);
                mma16n8k8(s[nt], qh[kc], bl);
                mma16n8k8(s[nt], ql[kc], bh);
                mma16n8k8(s[nt], qh[kc], bh);
            }
        }

        // causal mask (only the last block can cross the diagonal)
        if (kt == nblocks - 1) {
            #pragma unroll
            for (int nt = 0; nt < 16; nt++) {
                const int c0 = kv0 + nt * 8 + 2 * tg, c1 = c0 + 1;
                if (c0 > r0) s[nt][0] = -1e30f;
                if (c1 > r0) s[nt][1] = -1e30f;
                if (c0 > r1) s[nt][2] = -1e30f;
                if (c1 > r1) s[nt][3] = -1e30f;
            }
        }

        // online softmax
        float rmax0 = -1e30f, rmax1 = -1e30f;
        #pragma unroll
        for (int nt = 0; nt < 16; nt++) {
            rmax0 = fmaxf(rmax0, fmaxf(s[nt][0], s[nt][1]));
            rmax1 = fmaxf(rmax1, fmaxf(s[nt][2], s[nt][3]));
        }
        rmax0 = fmaxf(rmax0, __shfl_xor_sync(0xFFFFFFFFu, rmax0, 1));
        rmax0 = fmaxf(rmax0, __shfl_xor_sync(0xFFFFFFFFu, rmax0, 2));
        rmax1 = fmaxf(rmax1, __shfl_xor_sync(0xFFFFFFFFu, rmax1, 1));
        rmax1 = fmaxf(rmax1, __shfl_xor_sync(0xFFFFFFFFu, rmax1, 2));

        const float nm0 = fmaxf(m0, rmax0), nm1 = fmaxf(m1, rmax1);
        const float corr0 = __expf(m0 - nm0), corr1 = __expf(m1 - nm1);
        m0 = nm0; m1 = nm1;

        float ps0 = 0.f, ps1 = 0.f;
        #pragma unroll
        for (int nt = 0; nt < 16; nt++) {
            s[nt][0] = __expf(s[nt][0] - m0); ps0 += s[nt][0];
            s[nt][1] = __expf(s[nt][1] - m0); ps0 += s[nt][1];
            s[nt][2] = __expf(s[nt][2] - m1); ps1 += s[nt][2];
            s[nt][3] = __expf(s[nt][3] - m1); ps1 += s[nt][3];
        }
        l0 = l0 * corr0 + ps0;   // per-lane partial; reduced at the end
        l1 = l1 * corr1 + ps1;

        #pragma unroll
        for (int nt2 = 0; nt2 < 4; nt2++) {
            o[nt2][0] *= corr0; o[nt2][1] *= corr0;
            o[nt2][2] *= corr1; o[nt2][3] *= corr1;
        }

        // O += P * V (1xTF32). Re-layout P accum -> A-frag via shfl.
        const int src0 = (lane & ~3) | (tg >> 1);
        const int src1 = src0 + 2;
        const bool odd = (tg & 1);
        #pragma unroll
        for (int kc2 = 0; kc2 < 16; kc2++) {
            const float t00 = __shfl_sync(0xFFFFFFFFu, s[kc2][0], src0);
            const float t01 = __shfl_sync(0xFFFFFFFFu, s[kc2][1], src0);
            const float t10 = __shfl_sync(0xFFFFFFFFu, s[kc2][2], src0);
            const float t11 = __shfl_sync(0xFFFFFFFFu, s[kc2][3], src0);
            const float u00 = __shfl_sync(0xFFFFFFFFu, s[kc2][0], src1);
            const float u01 = __shfl_sync(0xFFFFFFFFu, s[kc2][1], src1);
            const float u10 = __shfl_sync(0xFFFFFFFFu, s[kc2][2], src1);
            const float u11 = __shfl_sync(0xFFFFFFFFu, s[kc2][3], src1);
            uint32_t a[4];
            a[0] = f32_to_tf32(odd ? t01 : t00);  // row r0, col kc2*8+tg
            a[1] = f32_to_tf32(odd ? t11 : t10);  // row r1, col kc2*8+tg
            a[2] = f32_to_tf32(odd ? u01 : u00);  // row r0, col kc2*8+tg+4
            a[3] = f32_to_tf32(odd ? u11 : u10);  // row r1, col kc2*8+tg+4
            #pragma unroll
            for (int nt2 = 0; nt2 < 4; nt2++) {
                uint32_t bb[2];
                bb[0] = f32_to_tf32(Vs[kc2 * 8 + tg    ][nt2 * 8 + g]);
                bb[1] = f32_to_tf32(Vs[kc2 * 8 + tg + 4][nt2 * 8 + g]);
                mma16n8k8(o[nt2], a, bb);
            }
        }
    }

    // final l reduction over the 4-lane quad, then normalize + write
    l0 += __shfl_xor_sync(0xFFFFFFFFu, l0, 1);
    l0 += __shfl_xor_sync(0xFFFFFFFFu, l0, 2);
    l1 += __shfl_xor_sync(0xFFFFFFFFu, l1, 1);
    l1 += __shfl_xor_sync(0xFFFFFFFFu, l1, 2);
    const float inv0 = 1.f / l0, inv1 = 1.f / l1;

    #pragma unroll
    for (int nt2 = 0; nt2 < 4; nt2++) {
        const int n = h * HDv + nt2 * 8 + 2 * tg;
        float2* p0 = (float2*)(Og + (size_t)(b * Sv + r0) * Dv + n);
        float2* p1 = (float2*)(Og + (size_t)(b * Sv + r1) * Dv + n);
        *p0 = make_float2(o[nt2][0] * inv0, o[nt2][1] * inv0);
        *p1 = make_float2(o[nt2][2] * inv1, o[nt2][3] * inv1);
    }
}

// ---------------------------------------------------------------------------
extern "C" void kernel_launch(void* const* d_in, const int* in_sizes, int n_in,
                              void* d_out, int out_size)
{
    const float* x      = (const float*)d_in[0];
    // d_in[1] = mask (additive causal, -1e9 above diag) -- handled analytically
    const float* slog   = (const float*)d_in[2];
    const float* wq     = (const float*)d_in[3];
    const float* wk     = (const float*)d_in[4];
    const float* wv     = (const float*)d_in[5];
    const float* wo     = (const float*)d_in[6];
    const float* sscale = (const float*)d_in[7];
    float* out = (float*)d_out;

    float *Qp, *Kp, *Vp, *Op;
    cudaGetSymbolAddress((void**)&Qp, g_Q);
    cudaGetSymbolAddress((void**)&Kp, g_K);
    cudaGetSymbolAddress((void**)&Vp, g_V);
    cudaGetSymbolAddress((void**)&Op, g_O);

    dim3 ggrd(Dv / 128, Mv / 128);   // (8, 32) = 256 CTAs

    gemm_mma<<<ggrd, 256>>>(x, wq, Qp, 1);
    gemm_mma<<<ggrd, 256>>>(x, wk, Kp, 1);
    gemm_mma<<<ggrd, 256>>>(x, wv, Vp, 1);

    dim3 fgrd(Sv / 64, Hv, Bv);      // (32, 32, 2) = 2048 CTAs
    flash_mma<<<fgrd, 128>>>(Qp, Kp, Vp, Op, slog, sscale);

    gemm_mma<<<ggrd, 256>>>(Op, wo, out, 0);
}

// round 6
// speedup vs baseline: 2.9534x; 1.4386x over previous
#include <cuda_runtime.h>
#include <cstdint>

// Problem constants
#define Bv 2
#define Sv 2048
#define Dv 1024
#define Hv 32
#define HDv 32
#define Mv (Bv*Sv)   // 4096

// Scratch (device globals -- no allocation allowed)
__device__ float g_Q[Bv*Hv*Sv*HDv];   // [b,h,s,hd]
__device__ float g_K[Bv*Hv*Sv*HDv];
__device__ float g_V[Bv*Hv*Sv*HDv];
__device__ float g_O[Mv*Dv];          // [b*s, h*hd] row-major

// ---------------------------------------------------------------------------
// helpers: tf32 (flash) + bf16 (GEMM) on the legacy mma.sync path
// ---------------------------------------------------------------------------
__device__ __forceinline__ uint32_t f32_to_tf32(float f) {
    uint32_t u;
    asm("cvt.rna.tf32.f32 %0, %1;" : "=r"(u) : "f"(f));
    return u;
}

__device__ __forceinline__ void mma16n8k8(float* d, const uint32_t* a, const uint32_t* b) {
    asm volatile(
        "mma.sync.aligned.m16n8k8.row.col.f32.tf32.tf32.f32 "
        "{%0,%1,%2,%3}, {%4,%5,%6,%7}, {%8,%9}, {%0,%1,%2,%3};"
        : "+f"(d[0]), "+f"(d[1]), "+f"(d[2]), "+f"(d[3])
        : "r"(a[0]), "r"(a[1]), "r"(a[2]), "r"(a[3]), "r"(b[0]), "r"(b[1]));
}

__device__ __forceinline__ void split_tf32(float a, uint32_t& hi, uint32_t& lo) {
    hi = f32_to_tf32(a);
    lo = f32_to_tf32(a - __uint_as_float(hi));
}

// bf16x2 pack: low half = bf16(e0), high half = bf16(e1)  (rn, unbiased)
__device__ __forceinline__ uint32_t pack_bf16x2(float e0, float e1) {
    uint32_t r;
    asm("cvt.rn.bf16x2.f32 %0, %1, %2;" : "=r"(r) : "f"(e1), "f"(e0));
    return r;
}
__device__ __forceinline__ float bf16lo_f(uint32_t u) { return __uint_as_float(u << 16); }
__device__ __forceinline__ float bf16hi_f(uint32_t u) { return __uint_as_float(u & 0xFFFF0000u); }

// D(16x8,f32) += A(16x16,bf16,row) * B(16x8,bf16,col)
__device__ __forceinline__ void mma16n8k16_bf16(float* d, const uint32_t* a, const uint32_t* b) {
    asm volatile(
        "mma.sync.aligned.m16n8k16.row.col.f32.bf16.bf16.f32 "
        "{%0,%1,%2,%3}, {%4,%5,%6,%7}, {%8,%9}, {%0,%1,%2,%3};"
        : "+f"(d[0]), "+f"(d[1]), "+f"(d[2]), "+f"(d[3])
        : "r"(a[0]), "r"(a[1]), "r"(a[2]), "r"(a[3]), "r"(b[0]), "r"(b[1]));
}

// ---------------------------------------------------------------------------
// Tensor-core NT GEMM (3-term bf16: hi*hi + hi*lo + lo*hi):
// C[m,n] = sum_k A[m,k]*W[n,k]; M=4096, N=1024, K=1024.
// CTA tile 128x128, K-chunk 32, 8 warps (4m x 2n), warp tile 32x64.
// Smem holds packed bf16x2 hi/lo planes, stride 20 words (conflict-free
// fragment reads: banks 20g+tg cover all 32). 96 k16-MMAs per chunk.
// mode 0: C row-major [M][Dv]; mode 1: head-split [b,h,s,hd].
// ---------------------------------------------------------------------------
__global__ __launch_bounds__(256) void gemm_mma(
    const float* __restrict__ A, const float* __restrict__ W,
    float* __restrict__ C, int mode)
{
    __shared__ uint32_t Ah[128][20];   // 16 pairs/row + pad
    __shared__ uint32_t Al[128][20];
    __shared__ uint32_t Bh[128][20];
    __shared__ uint32_t Bl[128][20];

    const int tid  = threadIdx.x;
    const int wid  = tid >> 5, lane = tid & 31;
    const int wm   = wid & 3,  wn   = wid >> 2;     // warp grid 4 x 2
    const int g    = lane >> 2, tg  = lane & 3;     // groupID / thread-in-group
    const int m0   = blockIdx.y * 128;
    const int n0   = blockIdx.x * 128;

    // gmem staging map: idx = tid + j*256 -> row = idx>>3 (via +32j), c4 = idx&7
    const int lrow = tid >> 3;    // 0..31
    const int lc4  = tid & 7;     // float4 slot within 32-float chunk
    const float* Ap = A + (size_t)(m0 + lrow) * Dv + lc4 * 4;
    const float* Wp = W + (size_t)(n0 + lrow) * Dv + lc4 * 4;

    float acc[2][8][4];
    #pragma unroll
    for (int mt = 0; mt < 2; mt++)
        #pragma unroll
        for (int nt = 0; nt < 8; nt++)
            #pragma unroll
            for (int i = 0; i < 4; i++) acc[mt][nt][i] = 0.f;

    float4 ra[4], rb[4];
    #pragma unroll
    for (int j = 0; j < 4; j++) {
        ra[j] = *(const float4*)(Ap + (size_t)(32 * j) * Dv);
        rb[j] = *(const float4*)(Wp + (size_t)(32 * j) * Dv);
    }

    for (int c = 0; c < 32; c++) {
        __syncthreads();   // previous chunk's compute done reading smem
        #pragma unroll
        for (int j = 0; j < 4; j++) {
            const int row = lrow + 32 * j;
            // A: hi/lo split, packed pairs
            uint32_t h0 = pack_bf16x2(ra[j].x, ra[j].y);
            uint32_t h1 = pack_bf16x2(ra[j].z, ra[j].w);
            uint32_t l0 = pack_bf16x2(ra[j].x - bf16lo_f(h0), ra[j].y - bf16hi_f(h0));
            uint32_t l1 = pack_bf16x2(ra[j].z - bf16lo_f(h1), ra[j].w - bf16hi_f(h1));
            *(uint2*)&Ah[row][lc4 * 2] = make_uint2(h0, h1);
            *(uint2*)&Al[row][lc4 * 2] = make_uint2(l0, l1);
            // B
            h0 = pack_bf16x2(rb[j].x, rb[j].y);
            h1 = pack_bf16x2(rb[j].z, rb[j].w);
            l0 = pack_bf16x2(rb[j].x - bf16lo_f(h0), rb[j].y - bf16hi_f(h0));
            l1 = pack_bf16x2(rb[j].z - bf16lo_f(h1), rb[j].w - bf16hi_f(h1));
            *(uint2*)&Bh[row][lc4 * 2] = make_uint2(h0, h1);
            *(uint2*)&Bl[row][lc4 * 2] = make_uint2(l0, l1);
        }
        __syncthreads();

        if (c < 31) {
            const int k0 = (c + 1) * 32;
            #pragma unroll
            for (int j = 0; j < 4; j++) {
                ra[j] = *(const float4*)(Ap + (size_t)(32 * j) * Dv + k0);
                rb[j] = *(const float4*)(Wp + (size_t)(32 * j) * Dv + k0);
            }
        }

        #pragma unroll
        for (int ks = 0; ks < 2; ks++) {     // two k16 sub-chunks
            const int kp = ks * 8;           // pair-index base
            uint32_t ah[2][4], al[2][4];
            #pragma unroll
            for (int mt = 0; mt < 2; mt++) {
                const int r = wm * 32 + mt * 16;
                ah[mt][0] = Ah[r + g    ][kp + tg];
                ah[mt][1] = Ah[r + g + 8][kp + tg];
                ah[mt][2] = Ah[r + g    ][kp + tg + 4];
                ah[mt][3] = Ah[r + g + 8][kp + tg + 4];
                al[mt][0] = Al[r + g    ][kp + tg];
                al[mt][1] = Al[r + g + 8][kp + tg];
                al[mt][2] = Al[r + g    ][kp + tg + 4];
                al[mt][3] = Al[r + g + 8][kp + tg + 4];
            }
            #pragma unroll
            for (int nt = 0; nt < 8; nt++) {
                const int n = wn * 64 + nt * 8 + g;
                uint32_t bh[2], bl[2];
                bh[0] = Bh[n][kp + tg];  bh[1] = Bh[n][kp + tg + 4];
                bl[0] = Bl[n][kp + tg];  bl[1] = Bl[n][kp + tg + 4];
                #pragma unroll
                for (int mt = 0; mt < 2; mt++) {
                    mma16n8k16_bf16(acc[mt][nt], ah[mt], bl);  // hi*lo
                    mma16n8k16_bf16(acc[mt][nt], al[mt], bh);  // lo*hi
                    mma16n8k16_bf16(acc[mt][nt], ah[mt], bh);  // hi*hi
                }
            }
        }
    }

    // Epilogue: c0 (row g, col 2tg), c1 (+1 col), c2/c3 (row g+8)
    #pragma unroll
    for (int mt = 0; mt < 2; mt++) {
        #pragma unroll
        for (int nt = 0; nt < 8; nt++) {
            const int m = m0 + wm * 32 + mt * 16 + g;
            const int n = n0 + wn * 64 + nt * 8 + tg * 2;
            if (mode == 0) {
                float2* p0 = (float2*)(C + (size_t)m * Dv + n);
                float2* p1 = (float2*)(C + (size_t)(m + 8) * Dv + n);
                *p0 = make_float2(acc[mt][nt][0], acc[mt][nt][1]);
                *p1 = make_float2(acc[mt][nt][2], acc[mt][nt][3]);
            } else {
                const int h = n / HDv, hd = n % HDv;
                const int b0_ = m / Sv, s0_ = m % Sv;
                const int b1_ = (m + 8) / Sv, s1_ = (m + 8) % Sv;
                float2* p0 = (float2*)(C + (size_t)((b0_ * Hv + h) * Sv + s0_) * HDv + hd);
                float2* p1 = (float2*)(C + (size_t)((b1_ * Hv + h) * Sv + s1_) * HDv + hd);
                *p0 = make_float2(acc[mt][nt][0], acc[mt][nt][1]);
                *p1 = make_float2(acc[mt][nt][2], acc[mt][nt][3]);
            }
        }
    }
}

// ---------------------------------------------------------------------------
// Tensor-core causal flash attention (unchanged from R4 -- verified).
// ---------------------------------------------------------------------------
__global__ __launch_bounds__(128) void flash_mma(
    const float* __restrict__ Qg, const float* __restrict__ Kg,
    const float* __restrict__ Vg, float* __restrict__ Og,
    const float* __restrict__ slog, const float* __restrict__ sscale)
{
    __shared__ float Ks[128][36];   // QK B-frag banks: 4g+tg (conflict-free)
    __shared__ float Vs[128][40];   // PV B-frag banks: 8tg+g (conflict-free)

    const int tid  = threadIdx.x;
    const int wid  = tid >> 5, lane = tid & 31;
    const int g    = lane >> 2, tg  = lane & 3;
    const int q0   = blockIdx.x * 64;
    const int h    = blockIdx.y, b = blockIdx.z;

    const float* qbase = Qg + (size_t)(b * Hv + h) * Sv * HDv;
    const float* kbase = Kg + (size_t)(b * Hv + h) * Sv * HDv;
    const float* vbase = Vg + (size_t)(b * Hv + h) * Sv * HDv;

    const int r0 = q0 + wid * 16 + g;
    const int r1 = r0 + 8;

    const float sc0 = slog[r0] * sscale[h] * 0.17677669529663687f;
    const float sc1 = slog[r1] * sscale[h] * 0.17677669529663687f;

    uint32_t qh[4][4], ql[4][4];
    #pragma unroll
    for (int kc = 0; kc < 4; kc++) {
        float v0 = qbase[(size_t)r0 * HDv + kc * 8 + tg    ] * sc0;
        float v1 = qbase[(size_t)r1 * HDv + kc * 8 + tg    ] * sc1;
        float v2 = qbase[(size_t)r0 * HDv + kc * 8 + tg + 4] * sc0;
        float v3 = qbase[(size_t)r1 * HDv + kc * 8 + tg + 4] * sc1;
        split_tf32(v0, qh[kc][0], ql[kc][0]);
        split_tf32(v1, qh[kc][1], ql[kc][1]);
        split_tf32(v2, qh[kc][2], ql[kc][2]);
        split_tf32(v3, qh[kc][3], ql[kc][3]);
    }

    float m0 = -1e30f, m1 = -1e30f, l0 = 0.f, l1 = 0.f;
    float o[4][4];
    #pragma unroll
    for (int nt2 = 0; nt2 < 4; nt2++)
        #pragma unroll
        for (int i = 0; i < 4; i++) o[nt2][i] = 0.f;

    const int nblocks = (q0 + 64 + 127) / 128;

    for (int kt = 0; kt < nblocks; kt++) {
        const int kv0 = kt * 128;
        __syncthreads();
        #pragma unroll
        for (int j = 0; j < 8; j++) {
            const int idx = tid + j * 128;
            const int row = idx >> 3, c4 = idx & 7;
            *(float4*)&Ks[row][c4 * 4] = *(const float4*)(kbase + (size_t)(kv0 + row) * HDv + c4 * 4);
            *(float4*)&Vs[row][c4 * 4] = *(const float4*)(vbase + (size_t)(kv0 + row) * HDv + c4 * 4);
        }
        __syncthreads();

        float s[16][4];
        #pragma unroll
        for (int nt = 0; nt < 16; nt++)
            #pragma unroll
            for (int i = 0; i < 4; i++) s[nt][i] = 0.f;

        #pragma unroll
        for (int kc = 0; kc < 4; kc++) {
            #pragma unroll
            for (int nt = 0; nt < 16; nt++) {
                uint32_t bh[2], bl[2];
                split_tf32(Ks[nt * 8 + g][kc * 8 + tg    ], bh[0], bl[0]);
                split_tf32(Ks[nt * 8 + g][kc * 8 + tg + 4], bh[1], bl[1]);
                mma16n8k8(s[nt], qh[kc], bl);
                mma16n8k8(s[nt], ql[kc], bh);
                mma16n8k8(s[nt], qh[kc], bh);
            }
        }

        if (kt == nblocks - 1) {
            #pragma unroll
            for (int nt = 0; nt < 16; nt++) {
                const int c0 = kv0 + nt * 8 + 2 * tg, c1 = c0 + 1;
                if (c0 > r0) s[nt][0] = -1e30f;
                if (c1 > r0) s[nt][1] = -1e30f;
                if (c0 > r1) s[nt][2] = -1e30f;
                if (c1 > r1) s[nt][3] = -1e30f;
            }
        }

        float rmax0 = -1e30f, rmax1 = -1e30f;
        #pragma unroll
        for (int nt = 0; nt < 16; nt++) {
            rmax0 = fmaxf(rmax0, fmaxf(s[nt][0], s[nt][1]));
            rmax1 = fmaxf(rmax1, fmaxf(s[nt][2], s[nt][3]));
        }
        rmax0 = fmaxf(rmax0, __shfl_xor_sync(0xFFFFFFFFu, rmax0, 1));
        rmax0 = fmaxf(rmax0, __shfl_xor_sync(0xFFFFFFFFu, rmax0, 2));
        rmax1 = fmaxf(rmax1, __shfl_xor_sync(0xFFFFFFFFu, rmax1, 1));
        rmax1 = fmaxf(rmax1, __shfl_xor_sync(0xFFFFFFFFu, rmax1, 2));

        const float nm0 = fmaxf(m0, rmax0), nm1 = fmaxf(m1, rmax1);
        const float corr0 = __expf(m0 - nm0), corr1 = __expf(m1 - nm1);
        m0 = nm0; m1 = nm1;

        float ps0 = 0.f, ps1 = 0.f;
        #pragma unroll
        for (int nt = 0; nt < 16; nt++) {
            s[nt][0] = __expf(s[nt][0] - m0); ps0 += s[nt][0];
            s[nt][1] = __expf(s[nt][1] - m0); ps0 += s[nt][1];
            s[nt][2] = __expf(s[nt][2] - m1); ps1 += s[nt][2];
            s[nt][3] = __expf(s[nt][3] - m1); ps1 += s[nt][3];
        }
        l0 = l0 * corr0 + ps0;
        l1 = l1 * corr1 + ps1;

        #pragma unroll
        for (int nt2 = 0; nt2 < 4; nt2++) {
            o[nt2][0] *= corr0; o[nt2][1] *= corr0;
            o[nt2][2] *= corr1; o[nt2][3] *= corr1;
        }

        const int src0 = (lane & ~3) | (tg >> 1);
        const int src1 = src0 + 2;
        const bool odd = (tg & 1);
        #pragma unroll
        for (int kc2 = 0; kc2 < 16; kc2++) {
            const float t00 = __shfl_sync(0xFFFFFFFFu, s[kc2][0], src0);
            const float t01 = __shfl_sync(0xFFFFFFFFu, s[kc2][1], src0);
            const float t10 = __shfl_sync(0xFFFFFFFFu, s[kc2][2], src0);
            const float t11 = __shfl_sync(0xFFFFFFFFu, s[kc2][3], src0);
            const float u00 = __shfl_sync(0xFFFFFFFFu, s[kc2][0], src1);
            const float u01 = __shfl_sync(0xFFFFFFFFu, s[kc2][1], src1);
            const float u10 = __shfl_sync(0xFFFFFFFFu, s[kc2][2], src1);
            const float u11 = __shfl_sync(0xFFFFFFFFu, s[kc2][3], src1);
            uint32_t a[4];
            a[0] = f32_to_tf32(odd ? t01 : t00);
            a[1] = f32_to_tf32(odd ? t11 : t10);
            a[2] = f32_to_tf32(odd ? u01 : u00);
            a[3] = f32_to_tf32(odd ? u11 : u10);
            #pragma unroll
            for (int nt2 = 0; nt2 < 4; nt2++) {
                uint32_t bb[2];
                bb[0] = f32_to_tf32(Vs[kc2 * 8 + tg    ][nt2 * 8 + g]);
                bb[1] = f32_to_tf32(Vs[kc2 * 8 + tg + 4][nt2 * 8 + g]);
                mma16n8k8(o[nt2], a, bb);
            }
        }
    }

    l0 += __shfl_xor_sync(0xFFFFFFFFu, l0, 1);
    l0 += __shfl_xor_sync(0xFFFFFFFFu, l0, 2);
    l1 += __shfl_xor_sync(0xFFFFFFFFu, l1, 1);
    l1 += __shfl_xor_sync(0xFFFFFFFFu, l1, 2);
    const float inv0 = 1.f / l0, inv1 = 1.f / l1;

    #pragma unroll
    for (int nt2 = 0; nt2 < 4; nt2++) {
        const int n = h * HDv + nt2 * 8 + 2 * tg;
        float2* p0 = (float2*)(Og + (size_t)(b * Sv + r0) * Dv + n);
        float2* p1 = (float2*)(Og + (size_t)(b * Sv + r1) * Dv + n);
        *p0 = make_float2(o[nt2][0] * inv0, o[nt2][1] * inv0);
        *p1 = make_float2(o[nt2][2] * inv1, o[nt2][3] * inv1);
    }
}

// ---------------------------------------------------------------------------
extern "C" void kernel_launch(void* const* d_in, const int* in_sizes, int n_in,
                              void* d_out, int out_size)
{
    const float* x      = (const float*)d_in[0];
    // d_in[1] = mask (additive causal, -1e9 above diag) -- handled analytically
    const float* slog   = (const float*)d_in[2];
    const float* wq     = (const float*)d_in[3];
    const float* wk     = (const float*)d_in[4];
    const float* wv     = (const float*)d_in[5];
    const float* wo     = (const float*)d_in[6];
    const float* sscale = (const float*)d_in[7];
    float* out = (float*)d_out;

    float *Qp, *Kp, *Vp, *Op;
    cudaGetSymbolAddress((void**)&Qp, g_Q);
    cudaGetSymbolAddress((void**)&Kp, g_K);
    cudaGetSymbolAddress((void**)&Vp, g_V);
    cudaGetSymbolAddress((void**)&Op, g_O);

    dim3 ggrd(Dv / 128, Mv / 128);   // (8, 32) = 256 CTAs

    gemm_mma<<<ggrd, 256>>>(x, wq, Qp, 1);
    gemm_mma<<<ggrd, 256>>>(x, wk, Kp, 1);
    gemm_mma<<<ggrd, 256>>>(x, wv, Vp, 1);

    dim3 fgrd(Sv / 64, Hv, Bv);      // (32, 32, 2) = 2048 CTAs
    flash_mma<<<fgrd, 128>>>(Qp, Kp, Vp, Op, slog, sscale);

    gemm_mma<<<ggrd, 256>>>(Op, wo, out, 0);
}

// round 7
// speedup vs baseline: 3.2273x; 1.0928x over previous
#include <cuda_runtime.h>
#include <cstdint>

// Problem constants
#define Bv 2
#define Sv 2048
#define Dv 1024
#define Hv 32
#define HDv 32
#define Mv (Bv*Sv)   // 4096

// Scratch (device globals -- no allocation allowed)
__device__ float g_Q[Bv*Hv*Sv*HDv];   // [b,h,s,hd]
__device__ float g_K[Bv*Hv*Sv*HDv];
__device__ float g_V[Bv*Hv*Sv*HDv];
__device__ float g_O[Mv*Dv];          // [b*s, h*hd] row-major

// ---------------------------------------------------------------------------
// bf16 helpers (legacy mma.sync path -- works on plain sm_103 target)
// ---------------------------------------------------------------------------
// bf16x2 pack: low half = bf16(e0), high half = bf16(e1)  (rn, unbiased)
__device__ __forceinline__ uint32_t pack_bf16x2(float e0, float e1) {
    uint32_t r;
    asm("cvt.rn.bf16x2.f32 %0, %1, %2;" : "=r"(r) : "f"(e1), "f"(e0));
    return r;
}
__device__ __forceinline__ float bf16lo_f(uint32_t u) { return __uint_as_float(u << 16); }
__device__ __forceinline__ float bf16hi_f(uint32_t u) { return __uint_as_float(u & 0xFFFF0000u); }

// D(16x8,f32) += A(16x16,bf16,row) * B(16x8,bf16,col)
__device__ __forceinline__ void mma16n8k16_bf16(float* d, const uint32_t* a, const uint32_t* b) {
    asm volatile(
        "mma.sync.aligned.m16n8k16.row.col.f32.bf16.bf16.f32 "
        "{%0,%1,%2,%3}, {%4,%5,%6,%7}, {%8,%9}, {%0,%1,%2,%3};"
        : "+f"(d[0]), "+f"(d[1]), "+f"(d[2]), "+f"(d[3])
        : "r"(a[0]), "r"(a[1]), "r"(a[2]), "r"(a[3]), "r"(b[0]), "r"(b[1]));
}

// pack a float pair into bf16x2 hi plane + lo (residual) plane
__device__ __forceinline__ void split_pack_bf16(float e0, float e1, uint32_t& hi, uint32_t& lo) {
    hi = pack_bf16x2(e0, e1);
    lo = pack_bf16x2(e0 - bf16lo_f(hi), e1 - bf16hi_f(hi));
}

// ---------------------------------------------------------------------------
// Tensor-core NT GEMM (3-term bf16) -- unchanged from R5, verified passing.
// C[m,n] = sum_k A[m,k]*W[n,k]; M=4096, N=1024, K=1024.
// ---------------------------------------------------------------------------
__global__ __launch_bounds__(256) void gemm_mma(
    const float* __restrict__ A, const float* __restrict__ W,
    float* __restrict__ C, int mode)
{
    __shared__ uint32_t Ah[128][20];
    __shared__ uint32_t Al[128][20];
    __shared__ uint32_t Bh[128][20];
    __shared__ uint32_t Bl[128][20];

    const int tid  = threadIdx.x;
    const int wid  = tid >> 5, lane = tid & 31;
    const int wm   = wid & 3,  wn   = wid >> 2;
    const int g    = lane >> 2, tg  = lane & 3;
    const int m0   = blockIdx.y * 128;
    const int n0   = blockIdx.x * 128;

    const int lrow = tid >> 3;
    const int lc4  = tid & 7;
    const float* Ap = A + (size_t)(m0 + lrow) * Dv + lc4 * 4;
    const float* Wp = W + (size_t)(n0 + lrow) * Dv + lc4 * 4;

    float acc[2][8][4];
    #pragma unroll
    for (int mt = 0; mt < 2; mt++)
        #pragma unroll
        for (int nt = 0; nt < 8; nt++)
            #pragma unroll
            for (int i = 0; i < 4; i++) acc[mt][nt][i] = 0.f;

    float4 ra[4], rb[4];
    #pragma unroll
    for (int j = 0; j < 4; j++) {
        ra[j] = *(const float4*)(Ap + (size_t)(32 * j) * Dv);
        rb[j] = *(const float4*)(Wp + (size_t)(32 * j) * Dv);
    }

    for (int c = 0; c < 32; c++) {
        __syncthreads();
        #pragma unroll
        for (int j = 0; j < 4; j++) {
            const int row = lrow + 32 * j;
            uint32_t h0, h1, l0, l1;
            split_pack_bf16(ra[j].x, ra[j].y, h0, l0);
            split_pack_bf16(ra[j].z, ra[j].w, h1, l1);
            *(uint2*)&Ah[row][lc4 * 2] = make_uint2(h0, h1);
            *(uint2*)&Al[row][lc4 * 2] = make_uint2(l0, l1);
            split_pack_bf16(rb[j].x, rb[j].y, h0, l0);
            split_pack_bf16(rb[j].z, rb[j].w, h1, l1);
            *(uint2*)&Bh[row][lc4 * 2] = make_uint2(h0, h1);
            *(uint2*)&Bl[row][lc4 * 2] = make_uint2(l0, l1);
        }
        __syncthreads();

        if (c < 31) {
            const int k0 = (c + 1) * 32;
            #pragma unroll
            for (int j = 0; j < 4; j++) {
                ra[j] = *(const float4*)(Ap + (size_t)(32 * j) * Dv + k0);
                rb[j] = *(const float4*)(Wp + (size_t)(32 * j) * Dv + k0);
            }
        }

        #pragma unroll
        for (int ks = 0; ks < 2; ks++) {
            const int kp = ks * 8;
            uint32_t ah[2][4], al[2][4];
            #pragma unroll
            for (int mt = 0; mt < 2; mt++) {
                const int r = wm * 32 + mt * 16;
                ah[mt][0] = Ah[r + g    ][kp + tg];
                ah[mt][1] = Ah[r + g + 8][kp + tg];
                ah[mt][2] = Ah[r + g    ][kp + tg + 4];
                ah[mt][3] = Ah[r + g + 8][kp + tg + 4];
                al[mt][0] = Al[r + g    ][kp + tg];
                al[mt][1] = Al[r + g + 8][kp + tg];
                al[mt][2] = Al[r + g    ][kp + tg + 4];
                al[mt][3] = Al[r + g + 8][kp + tg + 4];
            }
            #pragma unroll
            for (int nt = 0; nt < 8; nt++) {
                const int n = wn * 64 + nt * 8 + g;
                uint32_t bh[2], bl[2];
                bh[0] = Bh[n][kp + tg];  bh[1] = Bh[n][kp + tg + 4];
                bl[0] = Bl[n][kp + tg];  bl[1] = Bl[n][kp + tg + 4];
                #pragma unroll
                for (int mt = 0; mt < 2; mt++) {
                    mma16n8k16_bf16(acc[mt][nt], ah[mt], bl);
                    mma16n8k16_bf16(acc[mt][nt], al[mt], bh);
                    mma16n8k16_bf16(acc[mt][nt], ah[mt], bh);
                }
            }
        }
    }

    #pragma unroll
    for (int mt = 0; mt < 2; mt++) {
        #pragma unroll
        for (int nt = 0; nt < 8; nt++) {
            const int m = m0 + wm * 32 + mt * 16 + g;
            const int n = n0 + wn * 64 + nt * 8 + tg * 2;
            if (mode == 0) {
                float2* p0 = (float2*)(C + (size_t)m * Dv + n);
                float2* p1 = (float2*)(C + (size_t)(m + 8) * Dv + n);
                *p0 = make_float2(acc[mt][nt][0], acc[mt][nt][1]);
                *p1 = make_float2(acc[mt][nt][2], acc[mt][nt][3]);
            } else {
                const int h = n / HDv, hd = n % HDv;
                const int b0_ = m / Sv, s0_ = m % Sv;
                const int b1_ = (m + 8) / Sv, s1_ = (m + 8) % Sv;
                float2* p0 = (float2*)(C + (size_t)((b0_ * Hv + h) * Sv + s0_) * HDv + hd);
                float2* p1 = (float2*)(C + (size_t)((b1_ * Hv + h) * Sv + s1_) * HDv + hd);
                *p0 = make_float2(acc[mt][nt][0], acc[mt][nt][1]);
                *p1 = make_float2(acc[mt][nt][2], acc[mt][nt][3]);
            }
        }
    }
}

// ---------------------------------------------------------------------------
// Tensor-core causal flash attention, bf16 3-term, shfl-free P reuse.
// CTA: 64 q-rows, 4 warps; warp tile 16q x 128k. KV blocks of 128.
// QK^T: 3-term bf16 (K split once at staging). P*V: 3-term bf16 with the
// S-accumulator fragments repacked directly as A fragments (no shuffles).
// grid = (S/64, H, B), 128 threads.
// ---------------------------------------------------------------------------
__global__ __launch_bounds__(128) void flash_mma(
    const float* __restrict__ Qg, const float* __restrict__ Kg,
    const float* __restrict__ Vg, float* __restrict__ Og,
    const float* __restrict__ slog, const float* __restrict__ sscale)
{
    __shared__ uint32_t Ksh[128][20];   // K hi: [key][hd-pair], banks 20g+tg all-distinct
    __shared__ uint32_t Ksl[128][20];   // K lo
    __shared__ uint32_t Vsh[64][40];    // V hi: [key-pair][hd], banks 8tg+g all-distinct
    __shared__ uint32_t Vsl[64][40];    // V lo

    const int tid  = threadIdx.x;
    const int wid  = tid >> 5, lane = tid & 31;
    const int g    = lane >> 2, tg  = lane & 3;
    const int q0   = blockIdx.x * 64;
    const int h    = blockIdx.y, b = blockIdx.z;

    const float* qbase = Qg + (size_t)(b * Hv + h) * Sv * HDv;
    const float* kbase = Kg + (size_t)(b * Hv + h) * Sv * HDv;
    const float* vbase = Vg + (size_t)(b * Hv + h) * Sv * HDv;

    const int r0 = q0 + wid * 16 + g;   // accum rows (c0,c1)
    const int r1 = r0 + 8;              // (c2,c3)

    const float sc0 = slog[r0] * sscale[h] * 0.17677669529663687f;
    const float sc1 = slog[r1] * sscale[h] * 0.17677669529663687f;

    // Q fragments, bf16 hi/lo, k16 layout: a0=(r0, 2tg..+1) a1=(r1, 2tg..+1)
    // a2=(r0, 2tg+8..+9) a3=(r1, 2tg+8..+9); kc = two k16 chunks of HD=32.
    uint32_t qh[2][4], ql[2][4];
    #pragma unroll
    for (int kc = 0; kc < 2; kc++) {
        const int k0 = kc * 16 + 2 * tg;
        split_pack_bf16(qbase[(size_t)r0 * HDv + k0    ] * sc0,
                        qbase[(size_t)r0 * HDv + k0 + 1] * sc0, qh[kc][0], ql[kc][0]);
        split_pack_bf16(qbase[(size_t)r1 * HDv + k0    ] * sc1,
                        qbase[(size_t)r1 * HDv + k0 + 1] * sc1, qh[kc][1], ql[kc][1]);
        split_pack_bf16(qbase[(size_t)r0 * HDv + k0 + 8] * sc0,
                        qbase[(size_t)r0 * HDv + k0 + 9] * sc0, qh[kc][2], ql[kc][2]);
        split_pack_bf16(qbase[(size_t)r1 * HDv + k0 + 8] * sc1,
                        qbase[(size_t)r1 * HDv + k0 + 9] * sc1, qh[kc][3], ql[kc][3]);
    }

    float m0 = -1e30f, m1 = -1e30f, l0 = 0.f, l1 = 0.f;
    float o[4][4];
    #pragma unroll
    for (int nt2 = 0; nt2 < 4; nt2++)
        #pragma unroll
        for (int i = 0; i < 4; i++) o[nt2][i] = 0.f;

    // V staging map (fixed per thread): key pair p, hd half hh
    const int vp = tid & 63, vhh = tid >> 6;

    const int nblocks = (q0 + 64 + 127) / 128;

    for (int kt = 0; kt < nblocks; kt++) {
        const int kv0 = kt * 128;
        __syncthreads();
        // stage K: pairs along hd (no transpose)
        #pragma unroll
        for (int j = 0; j < 8; j++) {
            const int idx = tid + j * 128;
            const int row = idx >> 3, c4 = idx & 7;
            float4 kv = *(const float4*)(kbase + (size_t)(kv0 + row) * HDv + c4 * 4);
            uint32_t h0, h1, l0_, l1_;
            split_pack_bf16(kv.x, kv.y, h0, l0_);
            split_pack_bf16(kv.z, kv.w, h1, l1_);
            *(uint2*)&Ksh[row][c4 * 2] = make_uint2(h0, h1);
            *(uint2*)&Ksl[row][c4 * 2] = make_uint2(l0_, l1_);
        }
        // stage V: pairs along key (low half = even key)
        #pragma unroll
        for (int c = 0; c < 4; c++) {
            float4 v0 = *(const float4*)(vbase + (size_t)(kv0 + 2 * vp    ) * HDv + vhh * 16 + 4 * c);
            float4 v1 = *(const float4*)(vbase + (size_t)(kv0 + 2 * vp + 1) * HDv + vhh * 16 + 4 * c);
            uint32_t w0, w1, w2, w3, x0, x1, x2, x3;
            split_pack_bf16(v0.x, v1.x, w0, x0);
            split_pack_bf16(v0.y, v1.y, w1, x1);
            split_pack_bf16(v0.z, v1.z, w2, x2);
            split_pack_bf16(v0.w, v1.w, w3, x3);
            *(uint4*)&Vsh[vp][vhh * 16 + 4 * c] = make_uint4(w0, w1, w2, w3);
            *(uint4*)&Vsl[vp][vhh * 16 + 4 * c] = make_uint4(x0, x1, x2, x3);
        }
        __syncthreads();

        // S = Q K^T (3-term bf16). s[nt] covers key cols [kv0+nt*8, +8)
        float s[16][4];
        #pragma unroll
        for (int nt = 0; nt < 16; nt++)
            #pragma unroll
            for (int i = 0; i < 4; i++) s[nt][i] = 0.f;

        #pragma unroll
        for (int kc = 0; kc < 2; kc++) {
            const int kp = kc * 8;
            #pragma unroll
            for (int nt = 0; nt < 16; nt++) {
                const int row = nt * 8 + g;
                uint32_t bh[2], bl[2];
                bh[0] = Ksh[row][kp + tg];  bh[1] = Ksh[row][kp + tg + 4];
                bl[0] = Ksl[row][kp + tg];  bl[1] = Ksl[row][kp + tg + 4];
                mma16n8k16_bf16(s[nt], qh[kc], bl);
                mma16n8k16_bf16(s[nt], ql[kc], bh);
                mma16n8k16_bf16(s[nt], qh[kc], bh);
            }
        }

        // causal mask (only the last block crosses the diagonal)
        if (kt == nblocks - 1) {
            #pragma unroll
            for (int nt = 0; nt < 16; nt++) {
                const int c0 = kv0 + nt * 8 + 2 * tg, c1 = c0 + 1;
                if (c0 > r0) s[nt][0] = -1e30f;
                if (c1 > r0) s[nt][1] = -1e30f;
                if (c0 > r1) s[nt][2] = -1e30f;
                if (c1 > r1) s[nt][3] = -1e30f;
            }
        }

        // online softmax
        float rmax0 = -1e30f, rmax1 = -1e30f;
        #pragma unroll
        for (int nt = 0; nt < 16; nt++) {
            rmax0 = fmaxf(rmax0, fmaxf(s[nt][0], s[nt][1]));
            rmax1 = fmaxf(rmax1, fmaxf(s[nt][2], s[nt][3]));
        }
        rmax0 = fmaxf(rmax0, __shfl_xor_sync(0xFFFFFFFFu, rmax0, 1));
        rmax0 = fmaxf(rmax0, __shfl_xor_sync(0xFFFFFFFFu, rmax0, 2));
        rmax1 = fmaxf(rmax1, __shfl_xor_sync(0xFFFFFFFFu, rmax1, 1));
        rmax1 = fmaxf(rmax1, __shfl_xor_sync(0xFFFFFFFFu, rmax1, 2));

        const float nm0 = fmaxf(m0, rmax0), nm1 = fmaxf(m1, rmax1);
        const float corr0 = __expf(m0 - nm0), corr1 = __expf(m1 - nm1);
        m0 = nm0; m1 = nm1;

        float ps0 = 0.f, ps1 = 0.f;
        #pragma unroll
        for (int nt = 0; nt < 16; nt++) {
            s[nt][0] = __expf(s[nt][0] - m0); ps0 += s[nt][0];
            s[nt][1] = __expf(s[nt][1] - m0); ps0 += s[nt][1];
            s[nt][2] = __expf(s[nt][2] - m1); ps1 += s[nt][2];
            s[nt][3] = __expf(s[nt][3] - m1); ps1 += s[nt][3];
        }
        l0 = l0 * corr0 + ps0;
        l1 = l1 * corr1 + ps1;

        #pragma unroll
        for (int nt2 = 0; nt2 < 4; nt2++) {
            o[nt2][0] *= corr0; o[nt2][1] *= corr0;
            o[nt2][2] *= corr1; o[nt2][3] *= corr1;
        }

        // O += P * V (3-term bf16). S accum frags == A frags: no shuffles.
        #pragma unroll
        for (int kc2 = 0; kc2 < 8; kc2++) {
            uint32_t ph[4], pl[4];
            split_pack_bf16(s[2 * kc2    ][0], s[2 * kc2    ][1], ph[0], pl[0]);
            split_pack_bf16(s[2 * kc2    ][2], s[2 * kc2    ][3], ph[1], pl[1]);
            split_pack_bf16(s[2 * kc2 + 1][0], s[2 * kc2 + 1][1], ph[2], pl[2]);
            split_pack_bf16(s[2 * kc2 + 1][2], s[2 * kc2 + 1][3], ph[3], pl[3]);
            #pragma unroll
            for (int nt2 = 0; nt2 < 4; nt2++) {
                const int n = nt2 * 8 + g;
                uint32_t vh[2], vl[2];
                vh[0] = Vsh[kc2 * 8 + tg][n];  vh[1] = Vsh[kc2 * 8 + tg + 4][n];
                vl[0] = Vsl[kc2 * 8 + tg][n];  vl[1] = Vsl[kc2 * 8 + tg + 4][n];
                mma16n8k16_bf16(o[nt2], ph, vl);
                mma16n8k16_bf16(o[nt2], pl, vh);
                mma16n8k16_bf16(o[nt2], ph, vh);
            }
        }
    }

    // final l reduction over the 4-lane quad, normalize + write
    l0 += __shfl_xor_sync(0xFFFFFFFFu, l0, 1);
    l0 += __shfl_xor_sync(0xFFFFFFFFu, l0, 2);
    l1 += __shfl_xor_sync(0xFFFFFFFFu, l1, 1);
    l1 += __shfl_xor_sync(0xFFFFFFFFu, l1, 2);
    const float inv0 = 1.f / l0, inv1 = 1.f / l1;

    #pragma unroll
    for (int nt2 = 0; nt2 < 4; nt2++) {
        const int n = h * HDv + nt2 * 8 + 2 * tg;
        float2* p0 = (float2*)(Og + (size_t)(b * Sv + r0) * Dv + n);
        float2* p1 = (float2*)(Og + (size_t)(b * Sv + r1) * Dv + n);
        *p0 = make_float2(o[nt2][0] * inv0, o[nt2][1] * inv0);
        *p1 = make_float2(o[nt2][2] * inv1, o[nt2][3] * inv1);
    }
}

// ---------------------------------------------------------------------------
extern "C" void kernel_launch(void* const* d_in, const int* in_sizes, int n_in,
                              void* d_out, int out_size)
{
    const float* x      = (const float*)d_in[0];
    // d_in[1] = mask (additive causal, -1e9 above diag) -- handled analytically
    const float* slog   = (const float*)d_in[2];
    const float* wq     = (const float*)d_in[3];
    const float* wk     = (const float*)d_in[4];
    const float* wv     = (const float*)d_in[5];
    const float* wo     = (const float*)d_in[6];
    const float* sscale = (const float*)d_in[7];
    float* out = (float*)d_out;

    float *Qp, *Kp, *Vp, *Op;
    cudaGetSymbolAddress((void**)&Qp, g_Q);
    cudaGetSymbolAddress((void**)&Kp, g_K);
    cudaGetSymbolAddress((void**)&Vp, g_V);
    cudaGetSymbolAddress((void**)&Op, g_O);

    dim3 ggrd(Dv / 128, Mv / 128);   // (8, 32) = 256 CTAs

    gemm_mma<<<ggrd, 256>>>(x, wq, Qp, 1);
    gemm_mma<<<ggrd, 256>>>(x, wk, Kp, 1);
    gemm_mma<<<ggrd, 256>>>(x, wv, Vp, 1);

    dim3 fgrd(Sv / 64, Hv, Bv);      // (32, 32, 2) = 2048 CTAs
    flash_mma<<<fgrd, 128>>>(Qp, Kp, Vp, Op, slog, sscale);

    gemm_mma<<<ggrd, 256>>>(Op, wo, out, 0);
}